// round 9
// baseline (speedup 1.0000x reference)
#include <cuda_runtime.h>
#include <cstdint>
#include <cstddef>

#define NS     10
#define NPROJ  32
#define CCH    64
#define DD     9
#define DOUTD  4
#define PP1    2
#define PP2    4
#define PP3    4
#define PTOT   (PP1 + PP2 + PP3)
#define NT1    9
#define NT2    45
#define NT3    165
#define NT     (NT1 + NT2 + NT3)   // 219

#define CPB      4                 // channels per block (1 warp per channel)
#define NSTREAM  2                 // f32x2 streams per thread
#define NPB      (NSTREAM * 64)    // 128 nodes per block
#define NPAIRS   (NPB / 2)         // 64 node-pairs per channel
#define PAIR_W   18                // words per pair row (9 ull), conflict-free reads
#define XS_CC_W  (NPAIRS * PAIR_W + 8)  // 1160 words per channel
#define THREADS  128

#define SMEM_COEF_BYTES  (CPB * NT * 16)                     // 14016 (float4/monomial)
#define SMEM_XS_FLOATS   (CPB * XS_CC_W)                     // 4640
#define SMEM_BYTES       (SMEM_COEF_BYTES + SMEM_XS_FLOATS * 4)  // 32576

#define OUT_NODE_W 20              // out stage: 16 data words + 4 pad per node

typedef unsigned long long ull;

// Symmetrized coefficient table, NON-duplicated: [s][c][t] -> float4(u0..u3)
__device__ float4 g_Acoef[NS * CCH * NT];

__device__ __forceinline__ ull fmul2(ull a, ull b) {
    ull d; asm("mul.rn.f32x2 %0, %1, %2;" : "=l"(d) : "l"(a), "l"(b)); return d;
}
__device__ __forceinline__ ull ffma2(ull a, ull b, ull c) {
    ull d; asm("fma.rn.f32x2 %0, %1, %2, %3;" : "=l"(d) : "l"(a), "l"(b), "l"(c)); return d;
}
__device__ __forceinline__ float2 unpack2(ull v) {
    unsigned lo, hi; asm("mov.b64 {%0, %1}, %2;" : "=r"(lo), "=r"(hi) : "l"(v));
    return make_float2(__uint_as_float(lo), __uint_as_float(hi));
}
// Duplicate a scalar float into both halves of a 64-bit f32x2 operand (ALU MOV)
__device__ __forceinline__ ull dupf(float f) {
    ull d; asm("mov.b64 %0, {%1, %1};" : "=l"(d) : "f"(f)); return d;
}

// ---------------------------------------------------------------------------
// Prep: symmetrized coefficients  A[s][c][t] = float4 over u (non-duplicated)
// ---------------------------------------------------------------------------
__global__ void prep_kernel(const float* __restrict__ w,
                            const float* __restrict__ proj,
                            const float* __restrict__ u1,
                            const float* __restrict__ u2,
                            const float* __restrict__ u3) {
    int s = blockIdx.x / CCH;
    int c = blockIdx.x % CCH;
    __shared__ float wpv[PTOT];
    int tid = threadIdx.x;
    if (tid < PTOT) {
        float acc = 0.f;
        for (int a = 0; a < NPROJ; a++)
            acc += w[((size_t)s * NPROJ + a) * CCH + c] * proj[a * PTOT + tid];
        wpv[tid] = acc;
    }
    __syncthreads();

    for (int t = tid; t < NT; t += blockDim.x) {
        float cv[DOUTD];
        if (t < NT1) {
            int i = t;
            #pragma unroll
            for (int u = 0; u < DOUTD; u++) {
                float acc = 0.f;
                for (int p = 0; p < PP1; p++)
                    acc += u1[((size_t)u * DD + i) * PP1 + p] * wpv[p];
                cv[u] = acc;
            }
        } else if (t < NT1 + NT2) {
            int q = t - NT1;
            int i = 0, cnt = DD;
            while (q >= cnt) { q -= cnt; i++; cnt--; }
            int j = i + q;
            #pragma unroll
            for (int u = 0; u < DOUTD; u++) {
                float acc = 0.f;
                for (int p = 0; p < PP2; p++) {
                    float sym = u2[(((size_t)u * DD + i) * DD + j) * PP2 + p];
                    if (i != j) sym += u2[(((size_t)u * DD + j) * DD + i) * PP2 + p];
                    acc += sym * wpv[PP1 + p];
                }
                cv[u] = acc;
            }
        } else {
            int q = t - NT1 - NT2;
            int i = 0;
            for (;;) {
                int m = DD - i;
                int cnt = m * (m + 1) / 2;
                if (q < cnt) break;
                q -= cnt; i++;
            }
            int j = i;
            for (;;) {
                int cnt = DD - j;
                if (q < cnt) break;
                q -= cnt; j++;
            }
            int k = j + q;
            int pa[6], pb[6], pc[6], np = 0;
            if (i == j && j == k) {
                pa[0]=i; pb[0]=i; pc[0]=i; np = 1;
            } else if (i == j) {
                pa[0]=i; pb[0]=i; pc[0]=k;
                pa[1]=i; pb[1]=k; pc[1]=i;
                pa[2]=k; pb[2]=i; pc[2]=i; np = 3;
            } else if (j == k) {
                pa[0]=i; pb[0]=j; pc[0]=j;
                pa[1]=j; pb[1]=i; pc[1]=j;
                pa[2]=j; pb[2]=j; pc[2]=i; np = 3;
            } else {
                pa[0]=i; pb[0]=j; pc[0]=k;
                pa[1]=i; pb[1]=k; pc[1]=j;
                pa[2]=j; pb[2]=i; pc[2]=k;
                pa[3]=j; pb[3]=k; pc[3]=i;
                pa[4]=k; pb[4]=i; pc[4]=j;
                pa[5]=k; pb[5]=j; pc[5]=i; np = 6;
            }
            #pragma unroll
            for (int u = 0; u < DOUTD; u++) {
                float acc = 0.f;
                for (int m = 0; m < np; m++) {
                    const float* up = u3 + ((((size_t)u * DD + pa[m]) * DD + pb[m]) * DD + pc[m]) * PP3;
                    for (int p = 0; p < PP3; p++)
                        acc += up[p] * wpv[PP1 + PP2 + p];
                }
                cv[u] = acc;
            }
        }
        g_Acoef[((size_t)(s * CCH + c)) * NT + t] = make_float4(cv[0], cv[1], cv[2], cv[3]);
    }
}

// ---------------------------------------------------------------------------
// Fast evaluator: NSTR f32x2 node-packed streams. One LDS.128 per monomial
// (float4 over u), dup'd to f32x2 operands via register MOVs (ALU pipe).
// Results returned in registers.
// ---------------------------------------------------------------------------
template <int NSTR>
__device__ __forceinline__ void eval_streams(
    const float* __restrict__ xsS, const float4* __restrict__ cf4,
    ull (&acc)[NSTREAM][DOUTD], int wslot, int lane)
{
    ull xv[NSTR][DD];
    {
        const float* xb = xsS + wslot * XS_CC_W + lane * PAIR_W;
        #pragma unroll
        for (int v = 0; v < NSTR; v++)
            #pragma unroll
            for (int i = 0; i < DD; i++)
                xv[v][i] = *(const ull*)(xb + v * 32 * PAIR_W + 2 * i);
    }

    #pragma unroll
    for (int v = 0; v < NSTR; v++)
        #pragma unroll
        for (int u = 0; u < DOUTD; u++) acc[v][u] = 0;

    int t2 = NT1, t3 = NT1 + NT2;
    #pragma unroll
    for (int i = 0; i < DD; i++) {
        {
            float4 cw = cf4[i];
            ull c0 = dupf(cw.x), c1 = dupf(cw.y), c2 = dupf(cw.z), c3 = dupf(cw.w);
            #pragma unroll
            for (int v = 0; v < NSTR; v++) {
                acc[v][0] = ffma2(xv[v][i], c0, acc[v][0]);
                acc[v][1] = ffma2(xv[v][i], c1, acc[v][1]);
                acc[v][2] = ffma2(xv[v][i], c2, acc[v][2]);
                acc[v][3] = ffma2(xv[v][i], c3, acc[v][3]);
            }
        }
        #pragma unroll
        for (int j = i; j < DD; j++) {
            ull pij[NSTR];
            #pragma unroll
            for (int v = 0; v < NSTR; v++) pij[v] = fmul2(xv[v][i], xv[v][j]);
            {
                float4 cw = cf4[t2];
                ull c0 = dupf(cw.x), c1 = dupf(cw.y), c2 = dupf(cw.z), c3 = dupf(cw.w);
                #pragma unroll
                for (int v = 0; v < NSTR; v++) {
                    acc[v][0] = ffma2(pij[v], c0, acc[v][0]);
                    acc[v][1] = ffma2(pij[v], c1, acc[v][1]);
                    acc[v][2] = ffma2(pij[v], c2, acc[v][2]);
                    acc[v][3] = ffma2(pij[v], c3, acc[v][3]);
                }
            }
            t2++;
            #pragma unroll
            for (int k = j; k < DD; k++) {
                float4 cw = cf4[t3];
                ull c0 = dupf(cw.x), c1 = dupf(cw.y), c2 = dupf(cw.z), c3 = dupf(cw.w);
                #pragma unroll
                for (int v = 0; v < NSTR; v++) {
                    ull m = fmul2(pij[v], xv[v][k]);
                    acc[v][0] = ffma2(m, c0, acc[v][0]);
                    acc[v][1] = ffma2(m, c1, acc[v][1]);
                    acc[v][2] = ffma2(m, c2, acc[v][2]);
                    acc[v][3] = ffma2(m, c3, acc[v][3]);
                }
                t3++;
            }
        }
    }
}

// ---------------------------------------------------------------------------
// Main: per-species block assignment. grid = (ceil(N/128)+NS, 16), 128 thr,
// target 5 blocks/SM (regs<=102, smem 32576).
// ---------------------------------------------------------------------------
__global__ __launch_bounds__(THREADS, 5) void main_kernel(
    const float* __restrict__ x,
    const int* __restrict__ counts,
    float* __restrict__ out, int N)
{
    extern __shared__ char smemRaw[];
    float4* coefS = (float4*)smemRaw;
    float*  xsS   = (float*)(smemRaw + SMEM_COEF_BYTES);

    // ---- per-species block assignment (block-uniform walk over counts) ----
    int b = blockIdx.x;
    int sMy = -1, n0 = 0, avail = 0;
    {
        int base = 0;
        #pragma unroll 1
        for (int s = 0; s < NS; s++) {
            int cnt = counts[s];
            int nb  = (cnt + NPB - 1) / NPB;
            if (b < nb) {
                sMy   = s;
                n0    = base + b * NPB;
                avail = cnt - b * NPB;
                if (avail > NPB) avail = NPB;
                break;
            }
            b    -= nb;
            base += cnt;
        }
    }
    if (sMy < 0) return;

    const int c0  = blockIdx.y * CPB;
    const int tid = threadIdx.x;

    // Stage x with COALESCED global reads: consecutive idx -> consecutive
    // (cc,i) within a node (36 contiguous floats per node slice).
    // (n, cc, i) advanced incrementally (idx step 128 = 3 nodes + 2 cc + 2 i),
    // so no per-element div/mod.
    {
        int n   = tid / 36;
        int rem = tid - n * 36;
        int cc  = rem / 9;
        int i   = rem - cc * 9;
        #pragma unroll 1
        for (int it = 0; it < (NPB * CPB * DD) / THREADS; it++) {
            float v = (n < avail) ? x[((size_t)(n0 + n) * CCH + (c0 + cc)) * DD + i] : 0.f;
            xsS[cc * XS_CC_W + (n >> 1) * PAIR_W + 2 * i + (n & 1)] = v;
            n += 3; cc += 2; i += 2;
            if (i >= DD) { i -= DD; cc += 1; }
            if (cc >= CPB) { cc -= CPB; n += 1; }
        }
    }
    // Stage coefficients (float4 per monomial) for this (species, ch-group)
    {
        const float4* src = g_Acoef + ((size_t)(sMy * CCH + c0)) * NT;
        for (int idx = tid; idx < CPB * NT; idx += THREADS) coefS[idx] = src[idx];
    }
    __syncthreads();

    const int wslot = tid >> 5;
    const int lane  = tid & 31;
    const int vmax  = avail >> 6;          // full 64-node streams (block-uniform)

    const float4* cf4 = coefS + (size_t)wslot * NT;

    if (vmax > 0) {
        ull acc[NSTREAM][DOUTD];
        if (vmax >= 2) eval_streams<2>(xsS, cf4, acc, wslot, lane);
        else           eval_streams<1>(xsS, cf4, acc, wslot, lane);

        // All coefficient reads complete -> safe to reuse region for output
        __syncthreads();
        float* outS = (float*)coefS;       // [node][OUT_NODE_W]
        #pragma unroll
        for (int v = 0; v < NSTREAM; v++) {
            if (v >= vmax) break;
            float2 r0 = unpack2(acc[v][0]), r1 = unpack2(acc[v][1]);
            float2 r2 = unpack2(acc[v][2]), r3 = unpack2(acc[v][3]);
            int nodeBase = 64 * v + 2 * lane;
            *(float4*)(outS + (nodeBase + 0) * OUT_NODE_W + wslot * 4) =
                make_float4(r0.x, r1.x, r2.x, r3.x);
            *(float4*)(outS + (nodeBase + 1) * OUT_NODE_W + wslot * 4) =
                make_float4(r0.y, r1.y, r2.y, r3.y);
        }
        __syncthreads();
        // Coalesced cooperative store of vmax*64 nodes
        float4* out4 = (float4*)out;
        int total = (vmax << 6) * CPB;
        for (int g = tid; g < total; g += THREADS) {
            int node = g >> 2;
            int q    = g & 3;
            float4 vv = *(const float4*)(outS + node * OUT_NODE_W + q * 4);
            out4[(size_t)(n0 + node) * CCH + c0 + q] = vv;
        }
    }

    // Remainder nodes (avail % 64): scalar path (not taken for uniform counts)
    int remStart = vmax << 6;
    if (remStart < avail) {
        const int c = c0 + wslot;
        const float4* cfg = g_Acoef + ((size_t)(sMy * CCH + c)) * NT;
        #pragma unroll 1
        for (int k = remStart + lane; k < avail; k += 32) {
            float xs[DD];
            const float* xb = xsS + wslot * XS_CC_W + (k >> 1) * PAIR_W;
            #pragma unroll
            for (int i = 0; i < DD; i++) xs[i] = xb[2 * i + (k & 1)];
            float a[DOUTD] = {0.f, 0.f, 0.f, 0.f};
            int t2 = NT1, t3 = NT1 + NT2;
            #pragma unroll 1
            for (int i = 0; i < DD; i++) {
                float4 cw = cfg[i];
                a[0] += cw.x * xs[i]; a[1] += cw.y * xs[i];
                a[2] += cw.z * xs[i]; a[3] += cw.w * xs[i];
                #pragma unroll 1
                for (int j = i; j < DD; j++) {
                    float pij = xs[i] * xs[j];
                    float4 c2v = cfg[t2];
                    a[0] += c2v.x * pij; a[1] += c2v.y * pij;
                    a[2] += c2v.z * pij; a[3] += c2v.w * pij;
                    t2++;
                    #pragma unroll 1
                    for (int kk = j; kk < DD; kk++) {
                        float m = pij * xs[kk];
                        float4 c3v = cfg[t3];
                        a[0] += c3v.x * m; a[1] += c3v.y * m;
                        a[2] += c3v.z * m; a[3] += c3v.w * m;
                        t3++;
                    }
                }
            }
            float4* outp = (float4*)out;
            outp[(size_t)(n0 + k) * CCH + c] = make_float4(a[0], a[1], a[2], a[3]);
        }
    }
}

extern "C" void kernel_launch(void* const* d_in, const int* in_sizes, int n_in,
                              void* d_out, int out_size) {
    const float* x     = (const float*)d_in[0];
    const float* w     = (const float*)d_in[1];
    const float* proj  = (const float*)d_in[2];
    const float* u1    = (const float*)d_in[3];
    const float* u2    = (const float*)d_in[4];
    const float* u3    = (const float*)d_in[5];
    const int*   cnts  = (const int*)d_in[6];
    float* out = (float*)d_out;

    int N = in_sizes[0] / (CCH * DD);

    cudaFuncSetAttribute(main_kernel, cudaFuncAttributeMaxDynamicSharedMemorySize, SMEM_BYTES);

    prep_kernel<<<NS * CCH, 256>>>(w, proj, u1, u2, u3);

    dim3 grid((N + NPB - 1) / NPB + NS, CCH / CPB);
    main_kernel<<<grid, THREADS, SMEM_BYTES>>>(x, cnts, out, N);
}

// round 12
// speedup vs baseline: 1.2257x; 1.2257x over previous
#include <cuda_runtime.h>
#include <cstdint>
#include <cstddef>

#define NS     10
#define NPROJ  32
#define CCH    64
#define DD     9
#define DOUTD  4
#define PP1    2
#define PP2    4
#define PP3    4
#define PTOT   (PP1 + PP2 + PP3)
#define NT1    9
#define NT2    45
#define NT3    165
#define NT     (NT1 + NT2 + NT3)   // 219

#define CPB      2                 // channels per block (1 warp per channel)
#define NSTREAM  2                 // f32x2 streams per thread
#define NPB      (NSTREAM * 64)    // 128 nodes per block
#define NPAIRS   (NPB / 2)         // 64 node-pairs per channel
#define PAIR_W   18                // words per pair row (9 ull), conflict-free reads
#define XS_CC_W  (NPAIRS * PAIR_W + 8)  // 1160 words per channel
#define THREADS  64

#define SMEM_COEF_F2     (CPB * NT * DOUTD)                  // 1752 float2
#define SMEM_COEF_BYTES  (SMEM_COEF_F2 * 8)                  // 14016
#define SMEM_XS_FLOATS   (CPB * XS_CC_W)                     // 2320
#define SMEM_BYTES       (SMEM_COEF_BYTES + SMEM_XS_FLOATS * 4)  // 23296

#define OUT_NODE_W 12              // out stage words/node: 8 data + 4 pad.
                                   // 12*4=48 B per node, multiple of 16 ->
                                   // every float4 access stays aligned.

typedef unsigned long long ull;

// Symmetrized coefficient table: [s][c][t][u], each float2 = (v, v) duplicated
__device__ float2 g_Acoef[NS * CCH * NT * DOUTD];

__device__ __forceinline__ ull fmul2(ull a, ull b) {
    ull d; asm("mul.rn.f32x2 %0, %1, %2;" : "=l"(d) : "l"(a), "l"(b)); return d;
}
__device__ __forceinline__ ull ffma2(ull a, ull b, ull c) {
    ull d; asm("fma.rn.f32x2 %0, %1, %2, %3;" : "=l"(d) : "l"(a), "l"(b), "l"(c)); return d;
}
__device__ __forceinline__ float2 unpack2(ull v) {
    unsigned lo, hi; asm("mov.b64 {%0, %1}, %2;" : "=r"(lo), "=r"(hi) : "l"(v));
    return make_float2(__uint_as_float(lo), __uint_as_float(hi));
}

// ---------------------------------------------------------------------------
// Prep: symmetrized coefficients  A[s][c][t][u], duplicated (v,v) for f32x2
// ---------------------------------------------------------------------------
__global__ void prep_kernel(const float* __restrict__ w,
                            const float* __restrict__ proj,
                            const float* __restrict__ u1,
                            const float* __restrict__ u2,
                            const float* __restrict__ u3) {
    int s = blockIdx.x / CCH;
    int c = blockIdx.x % CCH;
    __shared__ float wpv[PTOT];
    int tid = threadIdx.x;
    if (tid < PTOT) {
        float acc = 0.f;
        for (int a = 0; a < NPROJ; a++)
            acc += w[((size_t)s * NPROJ + a) * CCH + c] * proj[a * PTOT + tid];
        wpv[tid] = acc;
    }
    __syncthreads();

    for (int t = tid; t < NT; t += blockDim.x) {
        float cv[DOUTD];
        if (t < NT1) {
            int i = t;
            #pragma unroll
            for (int u = 0; u < DOUTD; u++) {
                float acc = 0.f;
                for (int p = 0; p < PP1; p++)
                    acc += u1[((size_t)u * DD + i) * PP1 + p] * wpv[p];
                cv[u] = acc;
            }
        } else if (t < NT1 + NT2) {
            int q = t - NT1;
            int i = 0, cnt = DD;
            while (q >= cnt) { q -= cnt; i++; cnt--; }
            int j = i + q;
            #pragma unroll
            for (int u = 0; u < DOUTD; u++) {
                float acc = 0.f;
                for (int p = 0; p < PP2; p++) {
                    float sym = u2[(((size_t)u * DD + i) * DD + j) * PP2 + p];
                    if (i != j) sym += u2[(((size_t)u * DD + j) * DD + i) * PP2 + p];
                    acc += sym * wpv[PP1 + p];
                }
                cv[u] = acc;
            }
        } else {
            int q = t - NT1 - NT2;
            int i = 0;
            for (;;) {
                int m = DD - i;
                int cnt = m * (m + 1) / 2;
                if (q < cnt) break;
                q -= cnt; i++;
            }
            int j = i;
            for (;;) {
                int cnt = DD - j;
                if (q < cnt) break;
                q -= cnt; j++;
            }
            int k = j + q;
            int pa[6], pb[6], pc[6], np = 0;
            if (i == j && j == k) {
                pa[0]=i; pb[0]=i; pc[0]=i; np = 1;
            } else if (i == j) {
                pa[0]=i; pb[0]=i; pc[0]=k;
                pa[1]=i; pb[1]=k; pc[1]=i;
                pa[2]=k; pb[2]=i; pc[2]=i; np = 3;
            } else if (j == k) {
                pa[0]=i; pb[0]=j; pc[0]=j;
                pa[1]=j; pb[1]=i; pc[1]=j;
                pa[2]=j; pb[2]=j; pc[2]=i; np = 3;
            } else {
                pa[0]=i; pb[0]=j; pc[0]=k;
                pa[1]=i; pb[1]=k; pc[1]=j;
                pa[2]=j; pb[2]=i; pc[2]=k;
                pa[3]=j; pb[3]=k; pc[3]=i;
                pa[4]=k; pb[4]=i; pc[4]=j;
                pa[5]=k; pb[5]=j; pc[5]=i; np = 6;
            }
            #pragma unroll
            for (int u = 0; u < DOUTD; u++) {
                float acc = 0.f;
                for (int m = 0; m < np; m++) {
                    const float* up = u3 + ((((size_t)u * DD + pa[m]) * DD + pb[m]) * DD + pc[m]) * PP3;
                    for (int p = 0; p < PP3; p++)
                        acc += up[p] * wpv[PP1 + PP2 + p];
                }
                cv[u] = acc;
            }
        }
        float2* dst = g_Acoef + (((size_t)(s * CCH + c)) * NT + t) * DOUTD;
        #pragma unroll
        for (int u = 0; u < DOUTD; u++) dst[u] = make_float2(cv[u], cv[u]);
    }
}

// ---------------------------------------------------------------------------
// Fast evaluator: NSTR f32x2 streams; coefficients smem-broadcast as
// duplicated float2 (direct LDS.128 -> FFMA2 operands, no MOVs).
// Results returned in registers.
// ---------------------------------------------------------------------------
template <int NSTR>
__device__ __forceinline__ void eval_streams(
    const float* __restrict__ xsS, const float2* __restrict__ cf,
    ull (&acc)[NSTREAM][DOUTD], int wslot, int lane)
{
    ull xv[NSTR][DD];
    {
        const float* xb = xsS + wslot * XS_CC_W + lane * PAIR_W;
        #pragma unroll
        for (int v = 0; v < NSTR; v++)
            #pragma unroll
            for (int i = 0; i < DD; i++)
                xv[v][i] = *(const ull*)(xb + v * 32 * PAIR_W + 2 * i);
    }

    #pragma unroll
    for (int v = 0; v < NSTR; v++)
        #pragma unroll
        for (int u = 0; u < DOUTD; u++) acc[v][u] = 0;

    int t2 = NT1, t3 = NT1 + NT2;
    #pragma unroll
    for (int i = 0; i < DD; i++) {
        {
            const ulonglong2* cp = (const ulonglong2*)(cf + i * DOUTD);
            ulonglong2 lo = cp[0], hi = cp[1];
            #pragma unroll
            for (int v = 0; v < NSTR; v++) {
                acc[v][0] = ffma2(xv[v][i], lo.x, acc[v][0]);
                acc[v][1] = ffma2(xv[v][i], lo.y, acc[v][1]);
                acc[v][2] = ffma2(xv[v][i], hi.x, acc[v][2]);
                acc[v][3] = ffma2(xv[v][i], hi.y, acc[v][3]);
            }
        }
        #pragma unroll
        for (int j = i; j < DD; j++) {
            ull pij[NSTR];
            #pragma unroll
            for (int v = 0; v < NSTR; v++) pij[v] = fmul2(xv[v][i], xv[v][j]);
            {
                const ulonglong2* cp = (const ulonglong2*)(cf + t2 * DOUTD);
                ulonglong2 lo = cp[0], hi = cp[1];
                #pragma unroll
                for (int v = 0; v < NSTR; v++) {
                    acc[v][0] = ffma2(pij[v], lo.x, acc[v][0]);
                    acc[v][1] = ffma2(pij[v], lo.y, acc[v][1]);
                    acc[v][2] = ffma2(pij[v], hi.x, acc[v][2]);
                    acc[v][3] = ffma2(pij[v], hi.y, acc[v][3]);
                }
            }
            t2++;
            #pragma unroll
            for (int k = j; k < DD; k++) {
                const ulonglong2* cp = (const ulonglong2*)(cf + t3 * DOUTD);
                ulonglong2 lo = cp[0], hi = cp[1];
                #pragma unroll
                for (int v = 0; v < NSTR; v++) {
                    ull m = fmul2(pij[v], xv[v][k]);
                    acc[v][0] = ffma2(m, lo.x, acc[v][0]);
                    acc[v][1] = ffma2(m, lo.y, acc[v][1]);
                    acc[v][2] = ffma2(m, hi.x, acc[v][2]);
                    acc[v][3] = ffma2(m, hi.y, acc[v][3]);
                }
                t3++;
            }
        }
    }
}

// ---------------------------------------------------------------------------
// Main: per-species block assignment. grid = (ceil(N/128)+NS, 32), 64 thr,
// 9 blocks/SM (regs<=113, smem 23296) -> 18 warps/SM.
// ---------------------------------------------------------------------------
__global__ __launch_bounds__(THREADS, 9) void main_kernel(
    const float* __restrict__ x,
    const int* __restrict__ counts,
    float* __restrict__ out, int N)
{
    extern __shared__ char smemRaw[];
    float2* coefS = (float2*)smemRaw;
    float*  xsS   = (float*)(smemRaw + SMEM_COEF_BYTES);

    // ---- per-species block assignment (block-uniform walk over counts) ----
    int b = blockIdx.x;
    int sMy = -1, n0 = 0, avail = 0;
    {
        int base = 0;
        #pragma unroll 1
        for (int s = 0; s < NS; s++) {
            int cnt = counts[s];
            int nb  = (cnt + NPB - 1) / NPB;
            if (b < nb) {
                sMy   = s;
                n0    = base + b * NPB;
                avail = cnt - b * NPB;
                if (avail > NPB) avail = NPB;
                break;
            }
            b    -= nb;
            base += cnt;
        }
    }
    if (sMy < 0) return;

    const int c0  = blockIdx.y * CPB;
    const int tid = threadIdx.x;

    // Stage x into [cc][pair][2*i+parity]; pair stride 18 words (conflict-free
    // ull reads). tid -> (node-in-group, cc); 4 node groups x 9 i each.
    {
        const int nnB = tid >> 1;        // node within group (0..31)
        const int cc  = tid & 1;
        #pragma unroll
        for (int rep = 0; rep < NPB / 32; rep++) {
            int n = nnB + rep * 32;
            const float* xg = x + ((size_t)(n0 + n) * CCH + (c0 + cc)) * DD;
            float* xd = xsS + cc * XS_CC_W + (n >> 1) * PAIR_W + (n & 1);
            bool ok = (n < avail);
            #pragma unroll
            for (int i = 0; i < DD; i++)
                xd[2 * i] = ok ? xg[i] : 0.f;
        }
    }
    // Stage coefficients for this (species, channel pair)
    {
        const float4* src = (const float4*)(g_Acoef + ((size_t)(sMy * CCH + c0)) * NT * DOUTD);
        float4* dst = (float4*)coefS;
        for (int idx = tid; idx < SMEM_COEF_F2 / 2; idx += THREADS) dst[idx] = src[idx];
    }
    __syncthreads();

    const int wslot = tid >> 5;     // channel slot 0..1
    const int lane  = tid & 31;
    const int vmax  = avail >> 6;   // full 64-node streams (block-uniform)

    const float2* cf = coefS + (size_t)wslot * NT * DOUTD;

    if (vmax > 0) {
        ull acc[NSTREAM][DOUTD];
        if (vmax >= 2) eval_streams<2>(xsS, cf, acc, wslot, lane);
        else           eval_streams<1>(xsS, cf, acc, wslot, lane);

        // All coefficient reads complete -> safe to reuse region for output
        __syncthreads();
        float* outS = (float*)coefS;       // [node][OUT_NODE_W], 48 B/node
        #pragma unroll
        for (int v = 0; v < NSTREAM; v++) {
            if (v >= vmax) break;
            float2 r0 = unpack2(acc[v][0]), r1 = unpack2(acc[v][1]);
            float2 r2 = unpack2(acc[v][2]), r3 = unpack2(acc[v][3]);
            int nodeBase = 64 * v + 2 * lane;
            *(float4*)(outS + (nodeBase + 0) * OUT_NODE_W + wslot * 4) =
                make_float4(r0.x, r1.x, r2.x, r3.x);
            *(float4*)(outS + (nodeBase + 1) * OUT_NODE_W + wslot * 4) =
                make_float4(r0.y, r1.y, r2.y, r3.y);
        }
        __syncthreads();
        // Cooperative store: per node, channels c0..c0+1 = 32B contiguous
        float4* out4 = (float4*)out;
        int total = (vmax << 6) * CPB;
        for (int g = tid; g < total; g += THREADS) {
            int node = g >> 1;
            int q    = g & 1;
            float4 vv = *(const float4*)(outS + node * OUT_NODE_W + q * 4);
            out4[(size_t)(n0 + node) * CCH + c0 + q] = vv;
        }
    }

    // Remainder nodes (avail % 64): scalar path (not taken for uniform counts)
    int remStart = vmax << 6;
    if (remStart < avail) {
        const int c = c0 + wslot;
        const float2* cfg = g_Acoef + ((size_t)(sMy * CCH + c)) * NT * DOUTD;
        #pragma unroll 1
        for (int k = remStart + lane; k < avail; k += 32) {
            float xs[DD];
            const float* xb = xsS + wslot * XS_CC_W + (k >> 1) * PAIR_W;
            #pragma unroll
            for (int i = 0; i < DD; i++) xs[i] = xb[2 * i + (k & 1)];
            float a[DOUTD] = {0.f, 0.f, 0.f, 0.f};
            int t2 = NT1, t3 = NT1 + NT2;
            #pragma unroll 1
            for (int i = 0; i < DD; i++) {
                #pragma unroll
                for (int u = 0; u < DOUTD; u++) a[u] += cfg[i * DOUTD + u].x * xs[i];
                #pragma unroll 1
                for (int j = i; j < DD; j++) {
                    float pij = xs[i] * xs[j];
                    #pragma unroll
                    for (int u = 0; u < DOUTD; u++) a[u] += cfg[t2 * DOUTD + u].x * pij;
                    t2++;
                    #pragma unroll 1
                    for (int kk = j; kk < DD; kk++) {
                        float m = pij * xs[kk];
                        #pragma unroll
                        for (int u = 0; u < DOUTD; u++) a[u] += cfg[t3 * DOUTD + u].x * m;
                        t3++;
                    }
                }
            }
            float4* outp = (float4*)out;
            outp[(size_t)(n0 + k) * CCH + c] = make_float4(a[0], a[1], a[2], a[3]);
        }
    }
}

extern "C" void kernel_launch(void* const* d_in, const int* in_sizes, int n_in,
                              void* d_out, int out_size) {
    const float* x     = (const float*)d_in[0];
    const float* w     = (const float*)d_in[1];
    const float* proj  = (const float*)d_in[2];
    const float* u1    = (const float*)d_in[3];
    const float* u2    = (const float*)d_in[4];
    const float* u3    = (const float*)d_in[5];
    const int*   cnts  = (const int*)d_in[6];
    float* out = (float*)d_out;

    int N = in_sizes[0] / (CCH * DD);

    cudaFuncSetAttribute(main_kernel, cudaFuncAttributeMaxDynamicSharedMemorySize, SMEM_BYTES);

    prep_kernel<<<NS * CCH, 256>>>(w, proj, u1, u2, u3);

    dim3 grid((N + NPB - 1) / NPB + NS, CCH / CPB);
    main_kernel<<<grid, THREADS, SMEM_BYTES>>>(x, cnts, out, N);
}

// round 13
// speedup vs baseline: 1.6411x; 1.3389x over previous
#include <cuda_runtime.h>
#include <cstdint>
#include <cstddef>

#define NS     10
#define NPROJ  32
#define CCH    64
#define DD     9
#define DOUTD  4
#define PP1    2
#define PP2    4
#define PP3    4
#define PTOT   (PP1 + PP2 + PP3)
#define NT1    9
#define NT2    45
#define NT3    165
#define NT     (NT1 + NT2 + NT3)   // 219

#define CPB      4                 // channels per block (1 warp per channel)
#define NPS      4                 // scalar nodes per thread
#define NPB      (NPS * 32)        // 128 nodes per block
#define XS_CC_W  (NPB * DD + 8)    // 1160 words/channel; %32==8 -> conflict-free
#define THREADS  128

#define SMEM_COEF_BYTES  (CPB * NT * 16)                     // 14016 (float4/monomial)
#define SMEM_XS_FLOATS   (CPB * XS_CC_W)                     // 4640
#define SMEM_BYTES       (SMEM_COEF_BYTES + SMEM_XS_FLOATS * 4)  // 32576

#define OUT_NODE_W 20              // out stage: 16 data + 4 pad words = 80 B/node
                                   // (multiple of 16 B -> float4 aligned)

typedef unsigned long long ull;

// Symmetrized coefficient table, NON-duplicated: [s][c][t] -> float4(u0..u3)
__device__ float4 g_Acoef[NS * CCH * NT];

__device__ __forceinline__ ull ffma2(ull a, ull b, ull c) {
    ull d; asm("fma.rn.f32x2 %0, %1, %2, %3;" : "=l"(d) : "l"(a), "l"(b), "l"(c)); return d;
}
__device__ __forceinline__ float2 unpack2(ull v) {
    unsigned lo, hi; asm("mov.b64 {%0, %1}, %2;" : "=r"(lo), "=r"(hi) : "l"(v));
    return make_float2(__uint_as_float(lo), __uint_as_float(hi));
}
// Duplicate scalar float into both halves of an f32x2 operand (ALU MOV)
__device__ __forceinline__ ull dupf(float f) {
    ull d; asm("mov.b64 %0, {%1, %1};" : "=l"(d) : "f"(f)); return d;
}

// ---------------------------------------------------------------------------
// Prep: symmetrized coefficients  A[s][c][t] = float4 over u (non-duplicated)
// ---------------------------------------------------------------------------
__global__ void prep_kernel(const float* __restrict__ w,
                            const float* __restrict__ proj,
                            const float* __restrict__ u1,
                            const float* __restrict__ u2,
                            const float* __restrict__ u3) {
    int s = blockIdx.x / CCH;
    int c = blockIdx.x % CCH;
    __shared__ float wpv[PTOT];
    int tid = threadIdx.x;
    if (tid < PTOT) {
        float acc = 0.f;
        for (int a = 0; a < NPROJ; a++)
            acc += w[((size_t)s * NPROJ + a) * CCH + c] * proj[a * PTOT + tid];
        wpv[tid] = acc;
    }
    __syncthreads();

    for (int t = tid; t < NT; t += blockDim.x) {
        float cv[DOUTD];
        if (t < NT1) {
            int i = t;
            #pragma unroll
            for (int u = 0; u < DOUTD; u++) {
                float acc = 0.f;
                for (int p = 0; p < PP1; p++)
                    acc += u1[((size_t)u * DD + i) * PP1 + p] * wpv[p];
                cv[u] = acc;
            }
        } else if (t < NT1 + NT2) {
            int q = t - NT1;
            int i = 0, cnt = DD;
            while (q >= cnt) { q -= cnt; i++; cnt--; }
            int j = i + q;
            #pragma unroll
            for (int u = 0; u < DOUTD; u++) {
                float acc = 0.f;
                for (int p = 0; p < PP2; p++) {
                    float sym = u2[(((size_t)u * DD + i) * DD + j) * PP2 + p];
                    if (i != j) sym += u2[(((size_t)u * DD + j) * DD + i) * PP2 + p];
                    acc += sym * wpv[PP1 + p];
                }
                cv[u] = acc;
            }
        } else {
            int q = t - NT1 - NT2;
            int i = 0;
            for (;;) {
                int m = DD - i;
                int cnt = m * (m + 1) / 2;
                if (q < cnt) break;
                q -= cnt; i++;
            }
            int j = i;
            for (;;) {
                int cnt = DD - j;
                if (q < cnt) break;
                q -= cnt; j++;
            }
            int k = j + q;
            int pa[6], pb[6], pc[6], np = 0;
            if (i == j && j == k) {
                pa[0]=i; pb[0]=i; pc[0]=i; np = 1;
            } else if (i == j) {
                pa[0]=i; pb[0]=i; pc[0]=k;
                pa[1]=i; pb[1]=k; pc[1]=i;
                pa[2]=k; pb[2]=i; pc[2]=i; np = 3;
            } else if (j == k) {
                pa[0]=i; pb[0]=j; pc[0]=j;
                pa[1]=j; pb[1]=i; pc[1]=j;
                pa[2]=j; pb[2]=j; pc[2]=i; np = 3;
            } else {
                pa[0]=i; pb[0]=j; pc[0]=k;
                pa[1]=i; pb[1]=k; pc[1]=j;
                pa[2]=j; pb[2]=i; pc[2]=k;
                pa[3]=j; pb[3]=k; pc[3]=i;
                pa[4]=k; pb[4]=i; pc[4]=j;
                pa[5]=k; pb[5]=j; pc[5]=i; np = 6;
            }
            #pragma unroll
            for (int u = 0; u < DOUTD; u++) {
                float acc = 0.f;
                for (int m = 0; m < np; m++) {
                    const float* up = u3 + ((((size_t)u * DD + pa[m]) * DD + pb[m]) * DD + pc[m]) * PP3;
                    for (int p = 0; p < PP3; p++)
                        acc += up[p] * wpv[PP1 + PP2 + p];
                }
                cv[u] = acc;
            }
        }
        g_Acoef[((size_t)(s * CCH + c)) * NT + t] = make_float4(cv[0], cv[1], cv[2], cv[3]);
    }
}

// ---------------------------------------------------------------------------
// u-packed evaluator: 4 scalar nodes/thread; accumulators pack (u0,u1),(u2,u3).
// ONE LDS.128 per monomial gives both FFMA2 coefficient operands directly;
// the monomial value is duplicated per node via a single ALU MOV.
// ---------------------------------------------------------------------------
__device__ __forceinline__ void eval_upack(
    const float* __restrict__ xsS, const float4* __restrict__ cf4,
    ull (&acc)[NPS][2], int wslot, int lane)
{
    float xv[NPS][DD];
    {
        const float* xb = xsS + wslot * XS_CC_W + lane * DD;
        #pragma unroll
        for (int s = 0; s < NPS; s++)
            #pragma unroll
            for (int i = 0; i < DD; i++)
                xv[s][i] = xb[s * 32 * DD + i];
    }

    #pragma unroll
    for (int s = 0; s < NPS; s++) { acc[s][0] = 0; acc[s][1] = 0; }

    int t2 = NT1, t3 = NT1 + NT2;
    #pragma unroll
    for (int i = 0; i < DD; i++) {
        {
            ulonglong2 cw = *(const ulonglong2*)(cf4 + i);   // (c0,c1) (c2,c3)
            #pragma unroll
            for (int s = 0; s < NPS; s++) {
                ull d = dupf(xv[s][i]);
                acc[s][0] = ffma2(d, cw.x, acc[s][0]);
                acc[s][1] = ffma2(d, cw.y, acc[s][1]);
            }
        }
        #pragma unroll
        for (int j = i; j < DD; j++) {
            float pij[NPS];
            #pragma unroll
            for (int s = 0; s < NPS; s++) pij[s] = xv[s][i] * xv[s][j];
            {
                ulonglong2 cw = *(const ulonglong2*)(cf4 + t2);
                #pragma unroll
                for (int s = 0; s < NPS; s++) {
                    ull d = dupf(pij[s]);
                    acc[s][0] = ffma2(d, cw.x, acc[s][0]);
                    acc[s][1] = ffma2(d, cw.y, acc[s][1]);
                }
            }
            t2++;
            #pragma unroll
            for (int k = j; k < DD; k++) {
                ulonglong2 cw = *(const ulonglong2*)(cf4 + t3);
                #pragma unroll
                for (int s = 0; s < NPS; s++) {
                    float m = pij[s] * xv[s][k];
                    ull d = dupf(m);
                    acc[s][0] = ffma2(d, cw.x, acc[s][0]);
                    acc[s][1] = ffma2(d, cw.y, acc[s][1]);
                }
                t3++;
            }
        }
    }
}

// ---------------------------------------------------------------------------
// Main: per-species block assignment. grid = (ceil(N/128)+NS, 16), 128 thr,
// 4 blocks/SM (reg cap 128, smem 32576).
// ---------------------------------------------------------------------------
__global__ __launch_bounds__(THREADS, 4) void main_kernel(
    const float* __restrict__ x,
    const int* __restrict__ counts,
    float* __restrict__ out, int N)
{
    extern __shared__ char smemRaw[];
    float4* coefS = (float4*)smemRaw;
    float*  xsS   = (float*)(smemRaw + SMEM_COEF_BYTES);

    // ---- per-species block assignment (block-uniform walk over counts) ----
    int b = blockIdx.x;
    int sMy = -1, n0 = 0, avail = 0;
    {
        int base = 0;
        #pragma unroll 1
        for (int s = 0; s < NS; s++) {
            int cnt = counts[s];
            int nb  = (cnt + NPB - 1) / NPB;
            if (b < nb) {
                sMy   = s;
                n0    = base + b * NPB;
                avail = cnt - b * NPB;
                if (avail > NPB) avail = NPB;
                break;
            }
            b    -= nb;
            base += cnt;
        }
    }
    if (sMy < 0) return;

    const int c0  = blockIdx.y * CPB;
    const int tid = threadIdx.x;

    // Stage x scalar: xs[cc][node][i], node stride 9 (conflict-free reads);
    // channel pad (XS_CC_W%32==8) makes staging STS conflict-free too.
    {
        const int nnB = tid >> 2;        // node within group (0..31)
        const int cc  = tid & 3;
        #pragma unroll
        for (int rep = 0; rep < NPB / 32; rep++) {
            int n = nnB + rep * 32;
            const float* xg = x + ((size_t)(n0 + n) * CCH + (c0 + cc)) * DD;
            float* xd = xsS + cc * XS_CC_W + n * DD;
            bool ok = (n < avail);
            #pragma unroll
            for (int i = 0; i < DD; i++)
                xd[i] = ok ? xg[i] : 0.f;
        }
    }
    // Stage coefficients (float4 per monomial) for this (species, ch-group)
    {
        const float4* src = g_Acoef + ((size_t)(sMy * CCH + c0)) * NT;
        for (int idx = tid; idx < CPB * NT; idx += THREADS) coefS[idx] = src[idx];
    }
    __syncthreads();

    const int wslot = tid >> 5;
    const int lane  = tid & 31;
    const float4* cf4 = coefS + (size_t)wslot * NT;

    if (avail == NPB) {
        ull acc[NPS][2];
        eval_upack(xsS, cf4, acc, wslot, lane);

        // All coefficient reads complete -> safe to reuse region for output
        __syncthreads();
        float* outS = (float*)coefS;       // [node][OUT_NODE_W], 80 B/node
        #pragma unroll
        for (int s = 0; s < NPS; s++) {
            float2 a01 = unpack2(acc[s][0]);
            float2 a23 = unpack2(acc[s][1]);
            int node = 32 * s + lane;
            *(float4*)(outS + node * OUT_NODE_W + wslot * 4) =
                make_float4(a01.x, a01.y, a23.x, a23.y);
        }
        __syncthreads();
        // Coalesced cooperative store: per node, 4 channels = 64 B contiguous
        float4* out4 = (float4*)out;
        for (int g = tid; g < NPB * CPB; g += THREADS) {
            int node = g >> 2;
            int q    = g & 3;
            float4 vv = *(const float4*)(outS + node * OUT_NODE_W + q * 4);
            out4[(size_t)(n0 + node) * CCH + c0 + q] = vv;
        }
    } else {
        // Cold path: partial blocks (not taken for uniform counts)
        const int c = c0 + wslot;
        const float4* cfg = g_Acoef + ((size_t)(sMy * CCH + c)) * NT;
        #pragma unroll 1
        for (int k = lane; k < avail; k += 32) {
            float xs[DD];
            const float* xb = xsS + wslot * XS_CC_W + k * DD;
            #pragma unroll
            for (int i = 0; i < DD; i++) xs[i] = xb[i];
            float a[DOUTD] = {0.f, 0.f, 0.f, 0.f};
            int t2 = NT1, t3 = NT1 + NT2;
            #pragma unroll 1
            for (int i = 0; i < DD; i++) {
                float4 cw = cfg[i];
                a[0] += cw.x * xs[i]; a[1] += cw.y * xs[i];
                a[2] += cw.z * xs[i]; a[3] += cw.w * xs[i];
                #pragma unroll 1
                for (int j = i; j < DD; j++) {
                    float pij = xs[i] * xs[j];
                    float4 c2v = cfg[t2];
                    a[0] += c2v.x * pij; a[1] += c2v.y * pij;
                    a[2] += c2v.z * pij; a[3] += c2v.w * pij;
                    t2++;
                    #pragma unroll 1
                    for (int kk = j; kk < DD; kk++) {
                        float m = pij * xs[kk];
                        float4 c3v = cfg[t3];
                        a[0] += c3v.x * m; a[1] += c3v.y * m;
                        a[2] += c3v.z * m; a[3] += c3v.w * m;
                        t3++;
                    }
                }
            }
            float4* outp = (float4*)out;
            outp[(size_t)(n0 + k) * CCH + c] = make_float4(a[0], a[1], a[2], a[3]);
        }
    }
}

extern "C" void kernel_launch(void* const* d_in, const int* in_sizes, int n_in,
                              void* d_out, int out_size) {
    const float* x     = (const float*)d_in[0];
    const float* w     = (const float*)d_in[1];
    const float* proj  = (const float*)d_in[2];
    const float* u1    = (const float*)d_in[3];
    const float* u2    = (const float*)d_in[4];
    const float* u3    = (const float*)d_in[5];
    const int*   cnts  = (const int*)d_in[6];
    float* out = (float*)d_out;

    int N = in_sizes[0] / (CCH * DD);

    cudaFuncSetAttribute(main_kernel, cudaFuncAttributeMaxDynamicSharedMemorySize, SMEM_BYTES);

    prep_kernel<<<NS * CCH, 256>>>(w, proj, u1, u2, u3);

    dim3 grid((N + NPB - 1) / NPB + NS, CCH / CPB);
    main_kernel<<<grid, THREADS, SMEM_BYTES>>>(x, cnts, out, N);
}

// round 15
// speedup vs baseline: 1.7331x; 1.0561x over previous
#include <cuda_runtime.h>
#include <cstdint>
#include <cstddef>

#define NS     10
#define NPROJ  32
#define CCH    64
#define DD     9
#define DOUTD  4
#define PP1    2
#define PP2    4
#define PP3    4
#define PTOT   (PP1 + PP2 + PP3)
#define NT1    9
#define NT2    45
#define NT3    165
#define NT     (NT1 + NT2 + NT3)   // 219

#define CPB      4                 // channels per block (1 warp per channel)
#define NPS      4                 // scalar nodes per thread
#define NPB      (NPS * 32)        // 128 nodes per block
#define XS_CC_W  (NPB * DD + 8)    // 1160 words/channel
#define THREADS  128

#define SMEM_COEF_BYTES  (CPB * NT * 16)                     // 14016 (float4/monomial)
#define SMEM_XS_FLOATS   (CPB * XS_CC_W)                     // 4640
#define SMEM_BYTES       (SMEM_COEF_BYTES + SMEM_XS_FLOATS * 4)  // 32576

#define OUT_NODE_W 20              // out stage: 16 data + 4 pad words = 80 B/node

typedef unsigned long long ull;

// Symmetrized coefficient table, NON-duplicated: [s][c][t] -> float4(u0..u3)
__device__ float4 g_Acoef[NS * CCH * NT];

__device__ __forceinline__ ull ffma2(ull a, ull b, ull c) {
    ull d; asm("fma.rn.f32x2 %0, %1, %2, %3;" : "=l"(d) : "l"(a), "l"(b), "l"(c)); return d;
}
__device__ __forceinline__ float2 unpack2(ull v) {
    unsigned lo, hi; asm("mov.b64 {%0, %1}, %2;" : "=r"(lo), "=r"(hi) : "l"(v));
    return make_float2(__uint_as_float(lo), __uint_as_float(hi));
}
// Duplicate scalar float into both halves of an f32x2 operand
__device__ __forceinline__ ull dupf(float f) {
    ull d; asm("mov.b64 %0, {%1, %1};" : "=l"(d) : "f"(f)); return d;
}

// ---------------------------------------------------------------------------
// Prep: symmetrized coefficients  A[s][c][t] = float4 over u (non-duplicated)
// ---------------------------------------------------------------------------
__global__ void prep_kernel(const float* __restrict__ w,
                            const float* __restrict__ proj,
                            const float* __restrict__ u1,
                            const float* __restrict__ u2,
                            const float* __restrict__ u3) {
    int s = blockIdx.x / CCH;
    int c = blockIdx.x % CCH;
    __shared__ float wpv[PTOT];
    int tid = threadIdx.x;
    if (tid < PTOT) {
        float acc = 0.f;
        for (int a = 0; a < NPROJ; a++)
            acc += w[((size_t)s * NPROJ + a) * CCH + c] * proj[a * PTOT + tid];
        wpv[tid] = acc;
    }
    __syncthreads();

    for (int t = tid; t < NT; t += blockDim.x) {
        float cv[DOUTD];
        if (t < NT1) {
            int i = t;
            #pragma unroll
            for (int u = 0; u < DOUTD; u++) {
                float acc = 0.f;
                for (int p = 0; p < PP1; p++)
                    acc += u1[((size_t)u * DD + i) * PP1 + p] * wpv[p];
                cv[u] = acc;
            }
        } else if (t < NT1 + NT2) {
            int q = t - NT1;
            int i = 0, cnt = DD;
            while (q >= cnt) { q -= cnt; i++; cnt--; }
            int j = i + q;
            #pragma unroll
            for (int u = 0; u < DOUTD; u++) {
                float acc = 0.f;
                for (int p = 0; p < PP2; p++) {
                    float sym = u2[(((size_t)u * DD + i) * DD + j) * PP2 + p];
                    if (i != j) sym += u2[(((size_t)u * DD + j) * DD + i) * PP2 + p];
                    acc += sym * wpv[PP1 + p];
                }
                cv[u] = acc;
            }
        } else {
            int q = t - NT1 - NT2;
            int i = 0;
            for (;;) {
                int m = DD - i;
                int cnt = m * (m + 1) / 2;
                if (q < cnt) break;
                q -= cnt; i++;
            }
            int j = i;
            for (;;) {
                int cnt = DD - j;
                if (q < cnt) break;
                q -= cnt; j++;
            }
            int k = j + q;
            int pa[6], pb[6], pc[6], np = 0;
            if (i == j && j == k) {
                pa[0]=i; pb[0]=i; pc[0]=i; np = 1;
            } else if (i == j) {
                pa[0]=i; pb[0]=i; pc[0]=k;
                pa[1]=i; pb[1]=k; pc[1]=i;
                pa[2]=k; pb[2]=i; pc[2]=i; np = 3;
            } else if (j == k) {
                pa[0]=i; pb[0]=j; pc[0]=j;
                pa[1]=j; pb[1]=i; pc[1]=j;
                pa[2]=j; pb[2]=j; pc[2]=i; np = 3;
            } else {
                pa[0]=i; pb[0]=j; pc[0]=k;
                pa[1]=i; pb[1]=k; pc[1]=j;
                pa[2]=j; pb[2]=i; pc[2]=k;
                pa[3]=j; pb[3]=k; pc[3]=i;
                pa[4]=k; pb[4]=i; pc[4]=j;
                pa[5]=k; pb[5]=j; pc[5]=i; np = 6;
            }
            #pragma unroll
            for (int u = 0; u < DOUTD; u++) {
                float acc = 0.f;
                for (int m = 0; m < np; m++) {
                    const float* up = u3 + ((((size_t)u * DD + pa[m]) * DD + pb[m]) * DD + pc[m]) * PP3;
                    for (int p = 0; p < PP3; p++)
                        acc += up[p] * wpv[PP1 + PP2 + p];
                }
                cv[u] = acc;
            }
        }
        g_Acoef[((size_t)(s * CCH + c)) * NT + t] = make_float4(cv[0], cv[1], cv[2], cv[3]);
    }
}

// ---------------------------------------------------------------------------
// Horner evaluator: 4 scalar nodes/thread; accumulators pack (u0,u1),(u2,u3).
//   out = sum_i x_i ( A1[i] + sum_{j>=i} x_j ( A2[ij] + sum_{k>=j} x_k A3[ijk] ))
// Every FMA-pipe op is an FFMA2; no monomial-construction FMULs.
// ---------------------------------------------------------------------------
__device__ __forceinline__ void eval_horner(
    const float* __restrict__ xsS, const float4* __restrict__ cf4,
    ull (&out)[NPS][2], int wslot, int lane)
{
    float xv[NPS][DD];
    {
        const float* xb = xsS + wslot * XS_CC_W + lane * DD;
        #pragma unroll
        for (int s = 0; s < NPS; s++)
            #pragma unroll
            for (int i = 0; i < DD; i++)
                xv[s][i] = xb[s * 32 * DD + i];
    }

    #pragma unroll
    for (int s = 0; s < NPS; s++) { out[s][0] = 0; out[s][1] = 0; }

    int t2 = NT1, t3 = NT1 + NT2;
    #pragma unroll
    for (int i = 0; i < DD; i++) {
        ull S[NPS][2];
        {
            ulonglong2 c1 = *(const ulonglong2*)(cf4 + i);     // A1[i]: (u0,u1)(u2,u3)
            #pragma unroll
            for (int s = 0; s < NPS; s++) { S[s][0] = c1.x; S[s][1] = c1.y; }
        }
        #pragma unroll
        for (int j = i; j < DD; j++) {
            ull T[NPS][2];
            {
                ulonglong2 c2 = *(const ulonglong2*)(cf4 + t2); // A2[ij]
                #pragma unroll
                for (int s = 0; s < NPS; s++) { T[s][0] = c2.x; T[s][1] = c2.y; }
            }
            t2++;
            #pragma unroll
            for (int k = j; k < DD; k++) {
                ulonglong2 c3 = *(const ulonglong2*)(cf4 + t3); // A3[ijk]
                #pragma unroll
                for (int s = 0; s < NPS; s++) {
                    ull d = dupf(xv[s][k]);
                    T[s][0] = ffma2(d, c3.x, T[s][0]);
                    T[s][1] = ffma2(d, c3.y, T[s][1]);
                }
                t3++;
            }
            #pragma unroll
            for (int s = 0; s < NPS; s++) {
                ull d = dupf(xv[s][j]);
                S[s][0] = ffma2(d, T[s][0], S[s][0]);
                S[s][1] = ffma2(d, T[s][1], S[s][1]);
            }
        }
        #pragma unroll
        for (int s = 0; s < NPS; s++) {
            ull d = dupf(xv[s][i]);
            out[s][0] = ffma2(d, S[s][0], out[s][0]);
            out[s][1] = ffma2(d, S[s][1], out[s][1]);
        }
    }
}

// ---------------------------------------------------------------------------
// Main: per-species block assignment. grid = (ceil(N/128)+NS, 16), 128 thr,
// 4 blocks/SM (reg cap 128, smem 32576).
// ---------------------------------------------------------------------------
__global__ __launch_bounds__(THREADS, 4) void main_kernel(
    const float* __restrict__ x,
    const int* __restrict__ counts,
    float* __restrict__ out, int N)
{
    extern __shared__ char smemRaw[];
    float4* coefS = (float4*)smemRaw;
    float*  xsS   = (float*)(smemRaw + SMEM_COEF_BYTES);

    // ---- per-species block assignment (block-uniform walk over counts) ----
    int b = blockIdx.x;
    int sMy = -1, n0 = 0, avail = 0;
    {
        int base = 0;
        #pragma unroll 1
        for (int s = 0; s < NS; s++) {
            int cnt = counts[s];
            int nb  = (cnt + NPB - 1) / NPB;
            if (b < nb) {
                sMy   = s;
                n0    = base + b * NPB;
                avail = cnt - b * NPB;
                if (avail > NPB) avail = NPB;
                break;
            }
            b    -= nb;
            base += cnt;
        }
    }
    if (sMy < 0) return;

    const int c0  = blockIdx.y * CPB;
    const int tid = threadIdx.x;

    // Stage x scalar: xs[cc][node][i], node stride 9 words
    {
        const int nnB = tid >> 2;        // node within group (0..31)
        const int cc  = tid & 3;
        #pragma unroll
        for (int rep = 0; rep < NPB / 32; rep++) {
            int n = nnB + rep * 32;
            const float* xg = x + ((size_t)(n0 + n) * CCH + (c0 + cc)) * DD;
            float* xd = xsS + cc * XS_CC_W + n * DD;
            bool ok = (n < avail);
            #pragma unroll
            for (int i = 0; i < DD; i++)
                xd[i] = ok ? xg[i] : 0.f;
        }
    }
    // Stage coefficients (float4 per monomial) for this (species, ch-group)
    {
        const float4* src = g_Acoef + ((size_t)(sMy * CCH + c0)) * NT;
        for (int idx = tid; idx < CPB * NT; idx += THREADS) coefS[idx] = src[idx];
    }
    __syncthreads();

    const int wslot = tid >> 5;
    const int lane  = tid & 31;
    const float4* cf4 = coefS + (size_t)wslot * NT;

    if (avail == NPB) {
        ull acc[NPS][2];
        eval_horner(xsS, cf4, acc, wslot, lane);

        // All coefficient reads complete -> safe to reuse region for output
        __syncthreads();
        float* outS = (float*)coefS;       // [node][OUT_NODE_W], 80 B/node
        #pragma unroll
        for (int s = 0; s < NPS; s++) {
            float2 a01 = unpack2(acc[s][0]);
            float2 a23 = unpack2(acc[s][1]);
            int node = 32 * s + lane;
            *(float4*)(outS + node * OUT_NODE_W + wslot * 4) =
                make_float4(a01.x, a01.y, a23.x, a23.y);
        }
        __syncthreads();
        // Coalesced cooperative store: per node, 4 channels = 64 B contiguous
        float4* out4 = (float4*)out;
        for (int g = tid; g < NPB * CPB; g += THREADS) {
            int node = g >> 2;
            int q    = g & 3;
            float4 vv = *(const float4*)(outS + node * OUT_NODE_W + q * 4);
            out4[(size_t)(n0 + node) * CCH + c0 + q] = vv;
        }
    } else {
        // Cold path: partial blocks (not taken for uniform counts)
        const int c = c0 + wslot;
        const float4* cfg = g_Acoef + ((size_t)(sMy * CCH + c)) * NT;
        #pragma unroll 1
        for (int k = lane; k < avail; k += 32) {
            float xs[DD];
            const float* xb = xsS + wslot * XS_CC_W + k * DD;
            #pragma unroll
            for (int i = 0; i < DD; i++) xs[i] = xb[i];
            float a[DOUTD] = {0.f, 0.f, 0.f, 0.f};
            int t2 = NT1, t3 = NT1 + NT2;
            #pragma unroll 1
            for (int i = 0; i < DD; i++) {
                float4 cw = cfg[i];
                a[0] += cw.x * xs[i]; a[1] += cw.y * xs[i];
                a[2] += cw.z * xs[i]; a[3] += cw.w * xs[i];
                #pragma unroll 1
                for (int j = i; j < DD; j++) {
                    float pij = xs[i] * xs[j];
                    float4 c2v = cfg[t2];
                    a[0] += c2v.x * pij; a[1] += c2v.y * pij;
                    a[2] += c2v.z * pij; a[3] += c2v.w * pij;
                    t2++;
                    #pragma unroll 1
                    for (int kk = j; kk < DD; kk++) {
                        float m = pij * xs[kk];
                        float4 c3v = cfg[t3];
                        a[0] += c3v.x * m; a[1] += c3v.y * m;
                        a[2] += c3v.z * m; a[3] += c3v.w * m;
                        t3++;
                    }
                }
            }
            float4* outp = (float4*)out;
            outp[(size_t)(n0 + k) * CCH + c] = make_float4(a[0], a[1], a[2], a[3]);
        }
    }
}

extern "C" void kernel_launch(void* const* d_in, const int* in_sizes, int n_in,
                              void* d_out, int out_size) {
    const float* x     = (const float*)d_in[0];
    const float* w     = (const float*)d_in[1];
    const float* proj  = (const float*)d_in[2];
    const float* u1    = (const float*)d_in[3];
    const float* u2    = (const float*)d_in[4];
    const float* u3    = (const float*)d_in[5];
    const int*   cnts  = (const int*)d_in[6];
    float* out = (float*)d_out;

    int N = in_sizes[0] / (CCH * DD);

    cudaFuncSetAttribute(main_kernel, cudaFuncAttributeMaxDynamicSharedMemorySize, SMEM_BYTES);

    prep_kernel<<<NS * CCH, 256>>>(w, proj, u1, u2, u3);

    dim3 grid((N + NPB - 1) / NPB + NS, CCH / CPB);
    main_kernel<<<grid, THREADS, SMEM_BYTES>>>(x, cnts, out, N);
}